// round 1
// baseline (speedup 1.0000x reference)
#include <cuda_runtime.h>

#define Bb 4
#define Tt 2048
#define Dd 1024
#define Hh 16
#define HSs 64
#define Mm (Bb*Tt)   // 8192

// ---------------- scratch (device globals: allocation-free) ----------------
__device__ float g_K   [Bb*Hh*Tt*HSs];  // [B,H,T,HS]
__device__ float g_V   [Bb*Hh*Tt*HSs];
__device__ float g_cat [Mm*Dd];         // attention output, [B,T,D]
__device__ float g_y   [Mm*Dd];         // cat@Wo + bo + x
__device__ float g_norm[Mm*Dd];         // LN1 output
__device__ float g_h1  [Mm*Dd];         // relu(norm@Wf1+bf1)
__device__ float g_z   [Mm*Dd];         // ff + norm + x

// ---------------- generic tiled SGEMM: 128x128x16, 256 thr, 8x8 ----------------
// BLAYOUT 0: W row-major [K,N]
// BLAYOUT 1: W head-blocked [H, K, 64]  (Wk/Wv layout), logical col n = h*64+s
// EPI 0: write C in [B,H,T,HS] layout (KV projection)
// EPI 1: C = acc + bias[n] + add1[m,n]                 (y = cat@Wo + bo + x)
// EPI 2: C = relu(acc + bias[n])                        (FFN1)
// EPI 3: C = acc + bias[n] + add1[m,n] + add2[m,n]      (z = ff + norm + x)
template<int BLAYOUT, int EPI>
__global__ void __launch_bounds__(256, 2) sgemm_k(
    const float* __restrict__ A, const float* __restrict__ W, float* __restrict__ C,
    const float* __restrict__ bias, const float* __restrict__ add1,
    const float* __restrict__ add2)
{
    const int K = 1024, N = 1024;
    __shared__ float As[16][128];   // transposed A tile: As[k][m]
    __shared__ float Bs[16][128];   // Bs[k][n]

    int tid = threadIdx.x;
    int bn = blockIdx.x, bm = blockIdx.y;
    int tx = tid & 15, ty = tid >> 4;

    float acc[8][8];
    #pragma unroll
    for (int i = 0; i < 8; i++)
        #pragma unroll
        for (int j = 0; j < 8; j++) acc[i][j] = 0.f;

    int a_row = tid >> 2;          // 0..63
    int a_col = (tid & 3) << 2;    // 0,4,8,12
    int b_row = tid >> 5;          // 0..7
    int b_col = (tid & 31) << 2;   // 0..124
    const float* Ab = A + (size_t)(bm * 128) * K;

    for (int k0 = 0; k0 < K; k0 += 16) {
        #pragma unroll
        for (int i = 0; i < 2; i++) {
            int r = a_row + i * 64;
            float4 v = *(const float4*)(Ab + (size_t)r * K + k0 + a_col);
            As[a_col + 0][r] = v.x; As[a_col + 1][r] = v.y;
            As[a_col + 2][r] = v.z; As[a_col + 3][r] = v.w;
        }
        #pragma unroll
        for (int i = 0; i < 2; i++) {
            int r  = b_row + i * 8;
            int gk = k0 + r;
            int gn = bn * 128 + b_col;
            float4 v;
            if (BLAYOUT == 0) {
                v = *(const float4*)(W + (size_t)gk * N + gn);
            } else {
                int h = gn >> 6, s = gn & 63;
                v = *(const float4*)(W + ((size_t)h * K + gk) * 64 + s);
            }
            *(float4*)&Bs[r][b_col] = v;
        }
        __syncthreads();
        #pragma unroll
        for (int kk = 0; kk < 16; kk++) {
            float ra[8], rb[8];
            *(float4*)&ra[0] = *(const float4*)&As[kk][ty * 8];
            *(float4*)&ra[4] = *(const float4*)&As[kk][ty * 8 + 4];
            *(float4*)&rb[0] = *(const float4*)&Bs[kk][tx * 8];
            *(float4*)&rb[4] = *(const float4*)&Bs[kk][tx * 8 + 4];
            #pragma unroll
            for (int i = 0; i < 8; i++)
                #pragma unroll
                for (int j = 0; j < 8; j++)
                    acc[i][j] = fmaf(ra[i], rb[j], acc[i][j]);
        }
        __syncthreads();
    }

    int row0 = bm * 128 + ty * 8;
    int col0 = bn * 128 + tx * 8;
    #pragma unroll
    for (int i = 0; i < 8; i++) {
        int m = row0 + i;
        #pragma unroll
        for (int j = 0; j < 8; j++) {
            int n = col0 + j;
            float v = acc[i][j];
            if (EPI == 0) {
                int b = m >> 11, t = m & 2047, h = n >> 6, s = n & 63;
                C[((((size_t)b * Hh + h) * Tt + t) << 6) + s] = v;
            } else if (EPI == 1) {
                size_t idx = (size_t)m * Dd + n;
                C[idx] = v + bias[n] + add1[idx];
            } else if (EPI == 2) {
                float u = v + bias[n];
                C[(size_t)m * Dd + n] = u > 0.f ? u : 0.f;
            } else {
                size_t idx = (size_t)m * Dd + n;
                C[idx] = v + bias[n] + add1[idx] + add2[idx];
            }
        }
    }
}

// ---------------- flash attention (q==k, scale=2^-30, causal) ----------------
// grid: (T/128, H, B); block 256. Query tile 128 rows, key tile 64.
// thread (tr=tid/16, tc=tid%16) owns S rows tr*8..+7, cols tc*4..+3 (same for O cols of HS=64).
__global__ void __launch_bounds__(256) attn_k(
    const float* __restrict__ Kg, const float* __restrict__ Vg,
    float* __restrict__ cat)
{
    constexpr int P = 65;  // smem pitch (floats), scalar access only
    extern __shared__ float sm[];
    float* Qs = sm;              // [128][65]
    float* Ks = Qs + 128 * P;    // [64][65]
    float* Vs = Ks + 64  * P;    // [64][65]
    float* Ps = Vs + 64  * P;    // [128][65]

    int qi = blockIdx.x, h = blockIdx.y, b = blockIdx.z;
    int tid = threadIdx.x;
    int tc = tid & 15, tr = tid >> 4;

    const float* Kb = Kg + (((size_t)b * Hh + h) * Tt) * HSs;
    const float* Vb = Vg + (((size_t)b * Hh + h) * Tt) * HSs;

    const float scale = 9.313225746154785e-10f;  // 64^-5 = 2^-30

    // load Q tile (rows qi*128..+127), pre-scaled
    #pragma unroll
    for (int i = 0; i < 8; i++) {
        int f = tid + i * 256;
        int r = f >> 4, c = (f & 15) << 2;
        float4 v = *(const float4*)(Kb + (size_t)(qi * 128 + r) * 64 + c);
        Qs[r * P + c + 0] = v.x * scale;
        Qs[r * P + c + 1] = v.y * scale;
        Qs[r * P + c + 2] = v.z * scale;
        Qs[r * P + c + 3] = v.w * scale;
    }

    float m[8], l[8], o[8][4];
    #pragma unroll
    for (int i = 0; i < 8; i++) {
        m[i] = -1e30f; l[i] = 0.f;
        #pragma unroll
        for (int q = 0; q < 4; q++) o[i][q] = 0.f;
    }

    int jmax = 2 * qi + 1;
    for (int j = 0; j <= jmax; j++) {
        __syncthreads();   // guard K/V/P overwrite vs prior reads (also orders Qs stores on j=0)
        // load K, V key tiles (rows j*64..+63); scalar smem stores (pitch 65)
        #pragma unroll
        for (int i = 0; i < 4; i++) {
            int f = tid + i * 256;
            int r = f >> 4, c = (f & 15) << 2;
            float4 kv = *(const float4*)(Kb + (size_t)(j * 64 + r) * 64 + c);
            float4 vv = *(const float4*)(Vb + (size_t)(j * 64 + r) * 64 + c);
            Ks[r * P + c + 0] = kv.x; Ks[r * P + c + 1] = kv.y;
            Ks[r * P + c + 2] = kv.z; Ks[r * P + c + 3] = kv.w;
            Vs[r * P + c + 0] = vv.x; Vs[r * P + c + 1] = vv.y;
            Vs[r * P + c + 2] = vv.z; Vs[r * P + c + 3] = vv.w;
        }
        __syncthreads();

        // S = Q K^T (scaled)
        float s[8][4];
        #pragma unroll
        for (int i = 0; i < 8; i++)
            #pragma unroll
            for (int q = 0; q < 4; q++) s[i][q] = 0.f;

        for (int k = 0; k < 64; k++) {
            float rb0 = Ks[(tc * 4 + 0) * P + k];
            float rb1 = Ks[(tc * 4 + 1) * P + k];
            float rb2 = Ks[(tc * 4 + 2) * P + k];
            float rb3 = Ks[(tc * 4 + 3) * P + k];
            #pragma unroll
            for (int i = 0; i < 8; i++) {
                float ra = Qs[(tr * 8 + i) * P + k];
                s[i][0] = fmaf(ra, rb0, s[i][0]);
                s[i][1] = fmaf(ra, rb1, s[i][1]);
                s[i][2] = fmaf(ra, rb2, s[i][2]);
                s[i][3] = fmaf(ra, rb3, s[i][3]);
            }
        }

        bool needmask = (j >= 2 * qi);

        // online softmax (row stats across the 16-lane tc group)
        #pragma unroll
        for (int i = 0; i < 8; i++) {
            if (needmask) {
                int grow = qi * 128 + tr * 8 + i;
                #pragma unroll
                for (int q = 0; q < 4; q++) {
                    int gcol = j * 64 + tc * 4 + q;
                    if (gcol > grow) s[i][q] = -1e30f;
                }
            }
            float mx = fmaxf(fmaxf(s[i][0], s[i][1]), fmaxf(s[i][2], s[i][3]));
            #pragma unroll
            for (int w = 8; w >= 1; w >>= 1)
                mx = fmaxf(mx, __shfl_xor_sync(0xffffffffu, mx, w));
            float mnew  = fmaxf(m[i], mx);
            float alpha = __expf(m[i] - mnew);
            m[i] = mnew;
            float rs = 0.f;
            #pragma unroll
            for (int q = 0; q < 4; q++) {
                float p = __expf(s[i][q] - mnew);
                s[i][q] = p;
                rs += p;
            }
            #pragma unroll
            for (int w = 8; w >= 1; w >>= 1)
                rs += __shfl_xor_sync(0xffffffffu, rs, w);
            l[i] = l[i] * alpha + rs;
            #pragma unroll
            for (int q = 0; q < 4; q++) o[i][q] *= alpha;
            // stage P to smem (conflict-free: lanes spread across banks)
            Ps[(tr * 8 + i) * P + tc * 4 + 0] = s[i][0];
            Ps[(tr * 8 + i) * P + tc * 4 + 1] = s[i][1];
            Ps[(tr * 8 + i) * P + tc * 4 + 2] = s[i][2];
            Ps[(tr * 8 + i) * P + tc * 4 + 3] = s[i][3];
        }
        __syncthreads();

        // O += P @ V
        for (int jj = 0; jj < 64; jj++) {
            float v0 = Vs[jj * P + tc * 4 + 0];
            float v1 = Vs[jj * P + tc * 4 + 1];
            float v2 = Vs[jj * P + tc * 4 + 2];
            float v3 = Vs[jj * P + tc * 4 + 3];
            #pragma unroll
            for (int i = 0; i < 8; i++) {
                float p = Ps[(tr * 8 + i) * P + jj];
                o[i][0] = fmaf(p, v0, o[i][0]);
                o[i][1] = fmaf(p, v1, o[i][1]);
                o[i][2] = fmaf(p, v2, o[i][2]);
                o[i][3] = fmaf(p, v3, o[i][3]);
            }
        }
    }

    // finalize: divide by l, write concat layout [B,T,D]
    #pragma unroll
    for (int i = 0; i < 8; i++) {
        float inv = 1.f / l[i];
        int grow = qi * 128 + tr * 8 + i;
        float4 outv;
        outv.x = o[i][0] * inv; outv.y = o[i][1] * inv;
        outv.z = o[i][2] * inv; outv.w = o[i][3] * inv;
        *(float4*)(cat + ((size_t)b * Tt + grow) * Dd + h * 64 + tc * 4) = outv;
    }
}

// ---------------- LayerNorm: one block per row of 1024 ----------------
__global__ void __launch_bounds__(256) ln_k(
    const float* __restrict__ in, const float* __restrict__ g,
    const float* __restrict__ bb, float* __restrict__ out)
{
    __shared__ float rs[8], rq[8];
    int row = blockIdx.x;
    const float4 v = ((const float4*)(in + (size_t)row * Dd))[threadIdx.x];
    float s = v.x + v.y + v.z + v.w;
    float q = v.x * v.x + v.y * v.y + v.z * v.z + v.w * v.w;
    #pragma unroll
    for (int w = 16; w >= 1; w >>= 1) {
        s += __shfl_xor_sync(0xffffffffu, s, w);
        q += __shfl_xor_sync(0xffffffffu, q, w);
    }
    int warp = threadIdx.x >> 5, lane = threadIdx.x & 31;
    if (lane == 0) { rs[warp] = s; rq[warp] = q; }
    __syncthreads();
    if (threadIdx.x == 0) {
        float ts = 0.f, tq = 0.f;
        #pragma unroll
        for (int i = 0; i < 8; i++) { ts += rs[i]; tq += rq[i]; }
        float mean = ts * (1.f / 1024.f);
        float var  = tq * (1.f / 1024.f) - mean * mean;
        rs[0] = mean;
        rq[0] = rsqrtf(var + 1e-5f);
    }
    __syncthreads();
    float mean = rs[0], inv = rq[0];
    const float4 g4 = ((const float4*)g )[threadIdx.x];
    const float4 b4 = ((const float4*)bb)[threadIdx.x];
    float4 ov;
    ov.x = (v.x - mean) * inv * g4.x + b4.x;
    ov.y = (v.y - mean) * inv * g4.y + b4.y;
    ov.z = (v.z - mean) * inv * g4.z + b4.z;
    ov.w = (v.w - mean) * inv * g4.w + b4.w;
    ((float4*)(out + (size_t)row * Dd))[threadIdx.x] = ov;
}

// ---------------- driver ----------------
extern "C" void kernel_launch(void* const* d_in, const int* in_sizes, int n_in,
                              void* d_out, int out_size)
{
    const float* x   = (const float*)d_in[0];
    const float* Wk  = (const float*)d_in[1];
    const float* Wv  = (const float*)d_in[2];
    const float* Wo  = (const float*)d_in[3];
    const float* bo  = (const float*)d_in[4];
    const float* g1  = (const float*)d_in[5];
    const float* b1  = (const float*)d_in[6];
    const float* Wf1 = (const float*)d_in[7];
    const float* bf1 = (const float*)d_in[8];
    const float* Wf2 = (const float*)d_in[9];
    const float* bf2 = (const float*)d_in[10];
    const float* g2  = (const float*)d_in[11];
    const float* b2  = (const float*)d_in[12];
    float* out = (float*)d_out;

    float *pK, *pV, *pcat, *py, *pnorm, *ph1, *pz;
    cudaGetSymbolAddress((void**)&pK,    g_K);
    cudaGetSymbolAddress((void**)&pV,    g_V);
    cudaGetSymbolAddress((void**)&pcat,  g_cat);
    cudaGetSymbolAddress((void**)&py,    g_y);
    cudaGetSymbolAddress((void**)&pnorm, g_norm);
    cudaGetSymbolAddress((void**)&ph1,   g_h1);
    cudaGetSymbolAddress((void**)&pz,    g_z);

    const int ATTN_SMEM = (128 + 64 + 64 + 128) * 65 * 4;  // 99840 B
    cudaFuncSetAttribute(attn_k, cudaFuncAttributeMaxDynamicSharedMemorySize, ATTN_SMEM);

    dim3 gg(8, 64), tb(256);

    // 1-2: K and V projections (head-blocked weights, output [B,H,T,HS])
    sgemm_k<1, 0><<<gg, tb>>>(x, Wk, pK, nullptr, nullptr, nullptr);
    sgemm_k<1, 0><<<gg, tb>>>(x, Wv, pV, nullptr, nullptr, nullptr);

    // 3: causal flash attention -> concat layout
    attn_k<<<dim3(Tt / 128, Hh, Bb), 256, ATTN_SMEM>>>(pK, pV, pcat);

    // 4: y = cat @ Wo + bo + x
    sgemm_k<0, 1><<<gg, tb>>>(pcat, Wo, py, bo, x, nullptr);

    // 5: norm = LN1(y)
    ln_k<<<Mm, 256>>>(py, g1, b1, pnorm);

    // 6: h1 = relu(norm @ Wf1 + bf1)
    sgemm_k<0, 2><<<gg, tb>>>(pnorm, Wf1, ph1, bf1, nullptr, nullptr);

    // 7: z = h1 @ Wf2 + bf2 + norm + x
    sgemm_k<0, 3><<<gg, tb>>>(ph1, Wf2, pz, bf2, pnorm, x);

    // 8: out = LN2(z)
    ln_k<<<Mm, 256>>>(pz, g2, b2, out);
}

// round 2
// speedup vs baseline: 1.8030x; 1.8030x over previous
#include <cuda_runtime.h>

#define Bb 4
#define Tt 2048
#define Dd 1024
#define Hh 16
#define HSs 64
#define Mm (Bb*Tt)   // 8192

// ---------------- scratch (device globals: allocation-free) ----------------
__device__ float g_K   [Bb*Hh*Tt*HSs];  // [B,H,T,HS]
__device__ float g_V   [Bb*Hh*Tt*HSs];
__device__ float g_cat [Mm*Dd];         // attention output, [B,T,D]
__device__ float g_y   [Mm*Dd];         // cat@Wo + bo + x
__device__ float g_norm[Mm*Dd];         // LN1 output
__device__ float g_h1  [Mm*Dd];         // relu(norm@Wf1+bf1)
__device__ float g_z   [Mm*Dd];         // ff + norm + x

// ---------------- TF32 helpers ----------------
__device__ __forceinline__ float tf32r(float x) {
    unsigned u;
    asm("cvt.rna.tf32.f32 %0, %1;" : "=r"(u) : "f"(x));
    return __uint_as_float(u);
}

__device__ __forceinline__ void mma_tf32(float* c, const unsigned* a, const unsigned* b) {
    asm volatile(
        "mma.sync.aligned.m16n8k8.row.col.f32.tf32.tf32.f32 "
        "{%0,%1,%2,%3}, {%4,%5,%6,%7}, {%8,%9}, {%0,%1,%2,%3};\n"
        : "+f"(c[0]), "+f"(c[1]), "+f"(c[2]), "+f"(c[3])
        : "r"(a[0]), "r"(a[1]), "r"(a[2]), "r"(a[3]), "r"(b[0]), "r"(b[1]));
}

// ---------------- TF32 tensor-core GEMM: 128x128x32, 256 thr, 8 warps ----------------
// Warp layout: 2(M) x 4(N), warp tile 64x32, mma m16n8k8: 4 mtiles x 4 ntiles.
// Smem: As[m][k] pitch 36 (frag reads conflict-free: banks 4q+r), double-buffered
//       Bs[k][n] pitch 136 (frag reads conflict-free: banks 8r+q), double-buffered
// BLAYOUT 0: W row-major [K,N]
// BLAYOUT 1: W head-blocked [H, K, 64]  (Wk/Wv layout), logical col n = h*64+s
// EPI 0: write C in [B,H,T,HS] layout (KV projection)
// EPI 1: C = acc + bias[n] + add1[m,n]                 (y = cat@Wo + bo + x)
// EPI 2: C = relu(acc + bias[n])                        (FFN1)
// EPI 3: C = acc + bias[n] + add1[m,n] + add2[m,n]      (z = ff + norm + x)
#define APITCH 36
#define BPITCH 136
#define ASZ (128*APITCH)   // 4608 floats per buffer
#define BSZ (32*BPITCH)    // 4352 floats per buffer
#define GEMM_SMEM ((2*ASZ + 2*BSZ)*4)   // 71680 bytes

template<int BLAYOUT, int EPI>
__global__ void __launch_bounds__(256, 2) tgemm_k(
    const float* __restrict__ A, const float* __restrict__ W, float* __restrict__ C,
    const float* __restrict__ bias, const float* __restrict__ add1,
    const float* __restrict__ add2)
{
    const int K = 1024, N = 1024;
    extern __shared__ float sm[];
    float* As = sm;            // 2 buffers of ASZ
    float* Bs = sm + 2 * ASZ;  // 2 buffers of BSZ

    const int tid = threadIdx.x;
    const int lane = tid & 31, wid = tid >> 5;
    const int bn = blockIdx.x, bm = blockIdx.y;
    const int wm = (wid >> 2) * 64;   // warp M offset in tile
    const int wn = (wid & 3) * 32;    // warp N offset in tile
    const int q = lane >> 2, r = lane & 3;

    float acc[16][4];
    #pragma unroll
    for (int i = 0; i < 16; i++)
        #pragma unroll
        for (int j = 0; j < 4; j++) acc[i][j] = 0.f;

    const float* Ab = A + (size_t)(bm * 128) * K;

    // global-load index precompute (A: m=f>>3, c=f&7; B: k=f>>5, c=f&31)
    float4 pf[4];

    // ---- helpers as macros (keep regs tight) ----
#define LOADG_A(kt)                                                          \
    {                                                                        \
        _Pragma("unroll")                                                    \
        for (int i = 0; i < 4; i++) {                                        \
            int f = tid + i * 256; int m_ = f >> 3, c_ = f & 7;              \
            pf[i] = *(const float4*)(Ab + (size_t)m_ * K + (kt) * 32 + 4 * c_); \
        }                                                                    \
    }
#define STS_A(buf)                                                           \
    {                                                                        \
        _Pragma("unroll")                                                    \
        for (int i = 0; i < 4; i++) {                                        \
            int f = tid + i * 256; int m_ = f >> 3, c_ = f & 7;              \
            float* p = As + (buf) * ASZ + m_ * APITCH + 4 * c_;              \
            p[0] = tf32r(pf[i].x); p[1] = tf32r(pf[i].y);                    \
            p[2] = tf32r(pf[i].z); p[3] = tf32r(pf[i].w);                    \
        }                                                                    \
    }
#define LOADG_B(kt)                                                          \
    {                                                                        \
        _Pragma("unroll")                                                    \
        for (int i = 0; i < 4; i++) {                                        \
            int f = tid + i * 256; int k_ = f >> 5, c_ = f & 31;             \
            if (BLAYOUT == 0) {                                              \
                pf[i] = *(const float4*)(W + (size_t)((kt) * 32 + k_) * N + bn * 128 + 4 * c_); \
            } else {                                                         \
                int n_ = bn * 128 + 4 * c_; int h_ = n_ >> 6, s_ = n_ & 63;  \
                pf[i] = *(const float4*)(W + ((size_t)h_ * K + (kt) * 32 + k_) * 64 + s_); \
            }                                                                \
        }                                                                    \
    }
#define STS_B(buf)                                                           \
    {                                                                        \
        _Pragma("unroll")                                                    \
        for (int i = 0; i < 4; i++) {                                        \
            int f = tid + i * 256; int k_ = f >> 5, c_ = f & 31;             \
            float* p = Bs + (buf) * BSZ + k_ * BPITCH + 4 * c_;              \
            p[0] = tf32r(pf[i].x); p[1] = tf32r(pf[i].y);                    \
            p[2] = tf32r(pf[i].z); p[3] = tf32r(pf[i].w);                    \
        }                                                                    \
    }
#define COMPUTE_KS(buf, ks)                                                  \
    {                                                                        \
        unsigned afr[4][4], bfr[4][2];                                       \
        const float* ab = As + (buf) * ASZ + (wm + q) * APITCH + (ks) * 8 + r; \
        _Pragma("unroll")                                                    \
        for (int mt = 0; mt < 4; mt++) {                                     \
            const float* p = ab + mt * 16 * APITCH;                          \
            afr[mt][0] = *(const unsigned*)(p);                              \
            afr[mt][1] = *(const unsigned*)(p + 8 * APITCH);                 \
            afr[mt][2] = *(const unsigned*)(p + 4);                          \
            afr[mt][3] = *(const unsigned*)(p + 8 * APITCH + 4);             \
        }                                                                    \
        const float* bb2 = Bs + (buf) * BSZ + ((ks) * 8 + r) * BPITCH + wn + q; \
        _Pragma("unroll")                                                    \
        for (int nt = 0; nt < 4; nt++) {                                     \
            bfr[nt][0] = *(const unsigned*)(bb2 + nt * 8);                   \
            bfr[nt][1] = *(const unsigned*)(bb2 + 4 * BPITCH + nt * 8);      \
        }                                                                    \
        _Pragma("unroll")                                                    \
        for (int mt = 0; mt < 4; mt++)                                       \
            _Pragma("unroll")                                                \
            for (int nt = 0; nt < 4; nt++)                                   \
                mma_tf32(acc[mt * 4 + nt], afr[mt], bfr[nt]);                \
    }

    // prologue: fill buffer 0
    LOADG_A(0); STS_A(0);
    LOADG_B(0); STS_B(0);
    __syncthreads();

    // main loop: 32 K-tiles, double buffered, A/B prefetch split to halve reg pressure
    for (int kt = 0; kt < 32; kt++) {
        int buf = kt & 1;
        bool more = (kt < 31);
        if (more) LOADG_A(kt + 1);
        COMPUTE_KS(buf, 0);
        COMPUTE_KS(buf, 1);
        if (more) { STS_A(buf ^ 1); LOADG_B(kt + 1); }
        COMPUTE_KS(buf, 2);
        COMPUTE_KS(buf, 3);
        if (more) STS_B(buf ^ 1);
        __syncthreads();
    }

    // ---- epilogue ----
    #pragma unroll
    for (int mt = 0; mt < 4; mt++) {
        #pragma unroll
        for (int half = 0; half < 2; half++) {
            int m = bm * 128 + wm + mt * 16 + q + half * 8;
            #pragma unroll
            for (int nt = 0; nt < 4; nt++) {
                int n = bn * 128 + wn + nt * 8 + 2 * r;
                float v0 = acc[mt * 4 + nt][half * 2 + 0];
                float v1 = acc[mt * 4 + nt][half * 2 + 1];
                if (EPI == 0) {
                    int b_ = m >> 11, t_ = m & 2047, h_ = n >> 6, s_ = n & 63;
                    float2 ov = make_float2(v0, v1);
                    *(float2*)(C + ((((size_t)b_ * Hh + h_) * Tt + t_) << 6) + s_) = ov;
                } else if (EPI == 1) {
                    size_t idx = (size_t)m * Dd + n;
                    float2 a1 = *(const float2*)(add1 + idx);
                    float2 ov = make_float2(v0 + bias[n] + a1.x, v1 + bias[n + 1] + a1.y);
                    *(float2*)(C + idx) = ov;
                } else if (EPI == 2) {
                    float u0 = v0 + bias[n], u1 = v1 + bias[n + 1];
                    float2 ov = make_float2(u0 > 0.f ? u0 : 0.f, u1 > 0.f ? u1 : 0.f);
                    *(float2*)(C + (size_t)m * Dd + n) = ov;
                } else {
                    size_t idx = (size_t)m * Dd + n;
                    float2 a1 = *(const float2*)(add1 + idx);
                    float2 a2 = *(const float2*)(add2 + idx);
                    float2 ov = make_float2(v0 + bias[n] + a1.x + a2.x,
                                            v1 + bias[n + 1] + a1.y + a2.y);
                    *(float2*)(C + idx) = ov;
                }
            }
        }
    }
#undef LOADG_A
#undef STS_A
#undef LOADG_B
#undef STS_B
#undef COMPUTE_KS
}

// ---------------- flash attention (q==k, scale=2^-30, causal) ----------------
// grid: (T/128, H, B); block 256. Query tile 128 rows, key tile 64.
__global__ void __launch_bounds__(256) attn_k(
    const float* __restrict__ Kg, const float* __restrict__ Vg,
    float* __restrict__ cat)
{
    constexpr int P = 65;
    extern __shared__ float sm[];
    float* Qs = sm;              // [128][65]
    float* Ks = Qs + 128 * P;    // [64][65]
    float* Vs = Ks + 64  * P;    // [64][65]
    float* Ps = Vs + 64  * P;    // [128][65]

    int qi = blockIdx.x, h = blockIdx.y, b = blockIdx.z;
    int tid = threadIdx.x;
    int tc = tid & 15, tr = tid >> 4;

    const float* Kb = Kg + (((size_t)b * Hh + h) * Tt) * HSs;
    const float* Vb = Vg + (((size_t)b * Hh + h) * Tt) * HSs;

    const float scale = 9.313225746154785e-10f;  // 64^-5 = 2^-30

    #pragma unroll
    for (int i = 0; i < 8; i++) {
        int f = tid + i * 256;
        int r = f >> 4, c = (f & 15) << 2;
        float4 v = *(const float4*)(Kb + (size_t)(qi * 128 + r) * 64 + c);
        Qs[r * P + c + 0] = v.x * scale;
        Qs[r * P + c + 1] = v.y * scale;
        Qs[r * P + c + 2] = v.z * scale;
        Qs[r * P + c + 3] = v.w * scale;
    }

    float m[8], l[8], o[8][4];
    #pragma unroll
    for (int i = 0; i < 8; i++) {
        m[i] = -1e30f; l[i] = 0.f;
        #pragma unroll
        for (int qq = 0; qq < 4; qq++) o[i][qq] = 0.f;
    }

    int jmax = 2 * qi + 1;
    for (int j = 0; j <= jmax; j++) {
        __syncthreads();
        #pragma unroll
        for (int i = 0; i < 4; i++) {
            int f = tid + i * 256;
            int r = f >> 4, c = (f & 15) << 2;
            float4 kv = *(const float4*)(Kb + (size_t)(j * 64 + r) * 64 + c);
            float4 vv = *(const float4*)(Vb + (size_t)(j * 64 + r) * 64 + c);
            Ks[r * P + c + 0] = kv.x; Ks[r * P + c + 1] = kv.y;
            Ks[r * P + c + 2] = kv.z; Ks[r * P + c + 3] = kv.w;
            Vs[r * P + c + 0] = vv.x; Vs[r * P + c + 1] = vv.y;
            Vs[r * P + c + 2] = vv.z; Vs[r * P + c + 3] = vv.w;
        }
        __syncthreads();

        float s[8][4];
        #pragma unroll
        for (int i = 0; i < 8; i++)
            #pragma unroll
            for (int qq = 0; qq < 4; qq++) s[i][qq] = 0.f;

        for (int k = 0; k < 64; k++) {
            float rb0 = Ks[(tc * 4 + 0) * P + k];
            float rb1 = Ks[(tc * 4 + 1) * P + k];
            float rb2 = Ks[(tc * 4 + 2) * P + k];
            float rb3 = Ks[(tc * 4 + 3) * P + k];
            #pragma unroll
            for (int i = 0; i < 8; i++) {
                float ra = Qs[(tr * 8 + i) * P + k];
                s[i][0] = fmaf(ra, rb0, s[i][0]);
                s[i][1] = fmaf(ra, rb1, s[i][1]);
                s[i][2] = fmaf(ra, rb2, s[i][2]);
                s[i][3] = fmaf(ra, rb3, s[i][3]);
            }
        }

        bool needmask = (j >= 2 * qi);

        #pragma unroll
        for (int i = 0; i < 8; i++) {
            if (needmask) {
                int grow = qi * 128 + tr * 8 + i;
                #pragma unroll
                for (int qq = 0; qq < 4; qq++) {
                    int gcol = j * 64 + tc * 4 + qq;
                    if (gcol > grow) s[i][qq] = -1e30f;
                }
            }
            float mx = fmaxf(fmaxf(s[i][0], s[i][1]), fmaxf(s[i][2], s[i][3]));
            #pragma unroll
            for (int w = 8; w >= 1; w >>= 1)
                mx = fmaxf(mx, __shfl_xor_sync(0xffffffffu, mx, w));
            float mnew  = fmaxf(m[i], mx);
            float alpha = __expf(m[i] - mnew);
            m[i] = mnew;
            float rs = 0.f;
            #pragma unroll
            for (int qq = 0; qq < 4; qq++) {
                float p = __expf(s[i][qq] - mnew);
                s[i][qq] = p;
                rs += p;
            }
            #pragma unroll
            for (int w = 8; w >= 1; w >>= 1)
                rs += __shfl_xor_sync(0xffffffffu, rs, w);
            l[i] = l[i] * alpha + rs;
            #pragma unroll
            for (int qq = 0; qq < 4; qq++) o[i][qq] *= alpha;
            Ps[(tr * 8 + i) * P + tc * 4 + 0] = s[i][0];
            Ps[(tr * 8 + i) * P + tc * 4 + 1] = s[i][1];
            Ps[(tr * 8 + i) * P + tc * 4 + 2] = s[i][2];
            Ps[(tr * 8 + i) * P + tc * 4 + 3] = s[i][3];
        }
        __syncthreads();

        for (int jj = 0; jj < 64; jj++) {
            float v0 = Vs[jj * P + tc * 4 + 0];
            float v1 = Vs[jj * P + tc * 4 + 1];
            float v2 = Vs[jj * P + tc * 4 + 2];
            float v3 = Vs[jj * P + tc * 4 + 3];
            #pragma unroll
            for (int i = 0; i < 8; i++) {
                float p = Ps[(tr * 8 + i) * P + jj];
                o[i][0] = fmaf(p, v0, o[i][0]);
                o[i][1] = fmaf(p, v1, o[i][1]);
                o[i][2] = fmaf(p, v2, o[i][2]);
                o[i][3] = fmaf(p, v3, o[i][3]);
            }
        }
    }

    #pragma unroll
    for (int i = 0; i < 8; i++) {
        float inv = 1.f / l[i];
        int grow = qi * 128 + tr * 8 + i;
        float4 outv;
        outv.x = o[i][0] * inv; outv.y = o[i][1] * inv;
        outv.z = o[i][2] * inv; outv.w = o[i][3] * inv;
        *(float4*)(cat + ((size_t)b * Tt + grow) * Dd + h * 64 + tc * 4) = outv;
    }
}

// ---------------- LayerNorm: one block per row of 1024 ----------------
__global__ void __launch_bounds__(256) ln_k(
    const float* __restrict__ in, const float* __restrict__ g,
    const float* __restrict__ bb, float* __restrict__ out)
{
    __shared__ float rs[8], rq[8];
    int row = blockIdx.x;
    const float4 v = ((const float4*)(in + (size_t)row * Dd))[threadIdx.x];
    float s = v.x + v.y + v.z + v.w;
    float q = v.x * v.x + v.y * v.y + v.z * v.z + v.w * v.w;
    #pragma unroll
    for (int w = 16; w >= 1; w >>= 1) {
        s += __shfl_xor_sync(0xffffffffu, s, w);
        q += __shfl_xor_sync(0xffffffffu, q, w);
    }
    int warp = threadIdx.x >> 5, lane = threadIdx.x & 31;
    if (lane == 0) { rs[warp] = s; rq[warp] = q; }
    __syncthreads();
    if (threadIdx.x == 0) {
        float ts = 0.f, tq = 0.f;
        #pragma unroll
        for (int i = 0; i < 8; i++) { ts += rs[i]; tq += rq[i]; }
        float mean = ts * (1.f / 1024.f);
        float var  = tq * (1.f / 1024.f) - mean * mean;
        rs[0] = mean;
        rq[0] = rsqrtf(var + 1e-5f);
    }
    __syncthreads();
    float mean = rs[0], inv = rq[0];
    const float4 g4 = ((const float4*)g )[threadIdx.x];
    const float4 b4 = ((const float4*)bb)[threadIdx.x];
    float4 ov;
    ov.x = (v.x - mean) * inv * g4.x + b4.x;
    ov.y = (v.y - mean) * inv * g4.y + b4.y;
    ov.z = (v.z - mean) * inv * g4.z + b4.z;
    ov.w = (v.w - mean) * inv * g4.w + b4.w;
    ((float4*)(out + (size_t)row * Dd))[threadIdx.x] = ov;
}

// ---------------- driver ----------------
extern "C" void kernel_launch(void* const* d_in, const int* in_sizes, int n_in,
                              void* d_out, int out_size)
{
    const float* x   = (const float*)d_in[0];
    const float* Wk  = (const float*)d_in[1];
    const float* Wv  = (const float*)d_in[2];
    const float* Wo  = (const float*)d_in[3];
    const float* bo  = (const float*)d_in[4];
    const float* g1  = (const float*)d_in[5];
    const float* b1  = (const float*)d_in[6];
    const float* Wf1 = (const float*)d_in[7];
    const float* bf1 = (const float*)d_in[8];
    const float* Wf2 = (const float*)d_in[9];
    const float* bf2 = (const float*)d_in[10];
    const float* g2  = (const float*)d_in[11];
    const float* b2  = (const float*)d_in[12];
    float* out = (float*)d_out;

    float *pK, *pV, *pcat, *py, *pnorm, *ph1, *pz;
    cudaGetSymbolAddress((void**)&pK,    g_K);
    cudaGetSymbolAddress((void**)&pV,    g_V);
    cudaGetSymbolAddress((void**)&pcat,  g_cat);
    cudaGetSymbolAddress((void**)&py,    g_y);
    cudaGetSymbolAddress((void**)&pnorm, g_norm);
    cudaGetSymbolAddress((void**)&ph1,   g_h1);
    cudaGetSymbolAddress((void**)&pz,    g_z);

    const int ATTN_SMEM = (128 + 64 + 64 + 128) * 65 * 4;  // 99840 B
    cudaFuncSetAttribute(attn_k, cudaFuncAttributeMaxDynamicSharedMemorySize, ATTN_SMEM);
    cudaFuncSetAttribute(tgemm_k<1,0>, cudaFuncAttributeMaxDynamicSharedMemorySize, GEMM_SMEM);
    cudaFuncSetAttribute(tgemm_k<0,1>, cudaFuncAttributeMaxDynamicSharedMemorySize, GEMM_SMEM);
    cudaFuncSetAttribute(tgemm_k<0,2>, cudaFuncAttributeMaxDynamicSharedMemorySize, GEMM_SMEM);
    cudaFuncSetAttribute(tgemm_k<0,3>, cudaFuncAttributeMaxDynamicSharedMemorySize, GEMM_SMEM);

    dim3 gg(8, 64), tb(256);

    // 1-2: K and V projections (head-blocked weights, output [B,H,T,HS])
    tgemm_k<1, 0><<<gg, tb, GEMM_SMEM>>>(x, Wk, pK, nullptr, nullptr, nullptr);
    tgemm_k<1, 0><<<gg, tb, GEMM_SMEM>>>(x, Wv, pV, nullptr, nullptr, nullptr);

    // 3: causal flash attention -> concat layout
    attn_k<<<dim3(Tt / 128, Hh, Bb), 256, ATTN_SMEM>>>(pK, pV, pcat);

    // 4: y = cat @ Wo + bo + x
    tgemm_k<0, 1><<<gg, tb, GEMM_SMEM>>>(pcat, Wo, py, bo, x, nullptr);

    // 5: norm = LN1(y)
    ln_k<<<Mm, 256>>>(py, g1, b1, pnorm);

    // 6: h1 = relu(norm @ Wf1 + bf1)
    tgemm_k<0, 2><<<gg, tb, GEMM_SMEM>>>(pnorm, Wf1, ph1, bf1, nullptr, nullptr);

    // 7: z = h1 @ Wf2 + bf2 + norm + x
    tgemm_k<0, 3><<<gg, tb, GEMM_SMEM>>>(ph1, Wf2, pz, bf2, pnorm, x);

    // 8: out = LN2(z)
    ln_k<<<Mm, 256>>>(pz, g2, b2, out);
}

// round 3
// speedup vs baseline: 3.3908x; 1.8807x over previous
#include <cuda_runtime.h>

#define Bb 4
#define Tt 2048
#define Dd 1024
#define Hh 16
#define HSs 64
#define Mm (Bb*Tt)   // 8192

// ---------------- scratch (device globals: allocation-free) ----------------
__device__ float g_K   [Bb*Hh*Tt*HSs];  // [B,H,T,HS]
__device__ float g_V   [Bb*Hh*Tt*HSs];
__device__ float g_cat [Mm*Dd];         // attention output, [B,T,D]
__device__ float g_y   [Mm*Dd];         // cat@Wo + bo + x
__device__ float g_norm[Mm*Dd];         // LN1 output
__device__ float g_h1  [Mm*Dd];         // relu(norm@Wf1+bf1)
__device__ float g_z   [Mm*Dd];         // ff + norm + x

// ---------------- TF32 helpers ----------------
__device__ __forceinline__ float tf32r(float x) {
    unsigned u;
    asm("cvt.rna.tf32.f32 %0, %1;" : "=r"(u) : "f"(x));
    return __uint_as_float(u);
}

__device__ __forceinline__ void mma_tf32(float* c, const unsigned* a, const unsigned* b) {
    asm volatile(
        "mma.sync.aligned.m16n8k8.row.col.f32.tf32.tf32.f32 "
        "{%0,%1,%2,%3}, {%4,%5,%6,%7}, {%8,%9}, {%0,%1,%2,%3};\n"
        : "+f"(c[0]), "+f"(c[1]), "+f"(c[2]), "+f"(c[3])
        : "r"(a[0]), "r"(a[1]), "r"(a[2]), "r"(a[3]), "r"(b[0]), "r"(b[1]));
}

// ---------------- TF32 tensor-core GEMM: 128x128x32, 256 thr, 8 warps ----------------
#define APITCH 36
#define BPITCH 136
#define ASZ (128*APITCH)
#define BSZ (32*BPITCH)
#define GEMM_SMEM ((2*ASZ + 2*BSZ)*4)   // 71680 bytes

template<int BLAYOUT, int EPI>
__global__ void __launch_bounds__(256, 2) tgemm_k(
    const float* __restrict__ A, const float* __restrict__ W, float* __restrict__ C,
    const float* __restrict__ bias, const float* __restrict__ add1,
    const float* __restrict__ add2)
{
    const int K = 1024, N = 1024;
    extern __shared__ float sm[];
    float* As = sm;
    float* Bs = sm + 2 * ASZ;

    const int tid = threadIdx.x;
    const int lane = tid & 31, wid = tid >> 5;
    const int bn = blockIdx.x, bm = blockIdx.y;
    const int wm = (wid >> 2) * 64;
    const int wn = (wid & 3) * 32;
    const int q = lane >> 2, r = lane & 3;

    float acc[16][4];
    #pragma unroll
    for (int i = 0; i < 16; i++)
        #pragma unroll
        for (int j = 0; j < 4; j++) acc[i][j] = 0.f;

    const float* Ab = A + (size_t)(bm * 128) * K;
    float4 pf[4];

#define LOADG_A(kt)                                                          \
    {                                                                        \
        _Pragma("unroll")                                                    \
        for (int i = 0; i < 4; i++) {                                        \
            int f = tid + i * 256; int m_ = f >> 3, c_ = f & 7;              \
            pf[i] = *(const float4*)(Ab + (size_t)m_ * K + (kt) * 32 + 4 * c_); \
        }                                                                    \
    }
#define STS_A(buf)                                                           \
    {                                                                        \
        _Pragma("unroll")                                                    \
        for (int i = 0; i < 4; i++) {                                        \
            int f = tid + i * 256; int m_ = f >> 3, c_ = f & 7;              \
            float* p = As + (buf) * ASZ + m_ * APITCH + 4 * c_;              \
            p[0] = tf32r(pf[i].x); p[1] = tf32r(pf[i].y);                    \
            p[2] = tf32r(pf[i].z); p[3] = tf32r(pf[i].w);                    \
        }                                                                    \
    }
#define LOADG_B(kt)                                                          \
    {                                                                        \
        _Pragma("unroll")                                                    \
        for (int i = 0; i < 4; i++) {                                        \
            int f = tid + i * 256; int k_ = f >> 5, c_ = f & 31;             \
            if (BLAYOUT == 0) {                                              \
                pf[i] = *(const float4*)(W + (size_t)((kt) * 32 + k_) * N + bn * 128 + 4 * c_); \
            } else {                                                         \
                int n_ = bn * 128 + 4 * c_; int h_ = n_ >> 6, s_ = n_ & 63;  \
                pf[i] = *(const float4*)(W + ((size_t)h_ * K + (kt) * 32 + k_) * 64 + s_); \
            }                                                                \
        }                                                                    \
    }
#define STS_B(buf)                                                           \
    {                                                                        \
        _Pragma("unroll")                                                    \
        for (int i = 0; i < 4; i++) {                                        \
            int f = tid + i * 256; int k_ = f >> 5, c_ = f & 31;             \
            float* p = Bs + (buf) * BSZ + k_ * BPITCH + 4 * c_;              \
            p[0] = tf32r(pf[i].x); p[1] = tf32r(pf[i].y);                    \
            p[2] = tf32r(pf[i].z); p[3] = tf32r(pf[i].w);                    \
        }                                                                    \
    }
#define COMPUTE_KS(buf, ks)                                                  \
    {                                                                        \
        unsigned afr[4][4], bfr[4][2];                                       \
        const float* ab = As + (buf) * ASZ + (wm + q) * APITCH + (ks) * 8 + r; \
        _Pragma("unroll")                                                    \
        for (int mt = 0; mt < 4; mt++) {                                     \
            const float* p = ab + mt * 16 * APITCH;                          \
            afr[mt][0] = *(const unsigned*)(p);                              \
            afr[mt][1] = *(const unsigned*)(p + 8 * APITCH);                 \
            afr[mt][2] = *(const unsigned*)(p + 4);                          \
            afr[mt][3] = *(const unsigned*)(p + 8 * APITCH + 4);             \
        }                                                                    \
        const float* bb2 = Bs + (buf) * BSZ + ((ks) * 8 + r) * BPITCH + wn + q; \
        _Pragma("unroll")                                                    \
        for (int nt = 0; nt < 4; nt++) {                                     \
            bfr[nt][0] = *(const unsigned*)(bb2 + nt * 8);                   \
            bfr[nt][1] = *(const unsigned*)(bb2 + 4 * BPITCH + nt * 8);      \
        }                                                                    \
        _Pragma("unroll")                                                    \
        for (int mt = 0; mt < 4; mt++)                                       \
            _Pragma("unroll")                                                \
            for (int nt = 0; nt < 4; nt++)                                   \
                mma_tf32(acc[mt * 4 + nt], afr[mt], bfr[nt]);                \
    }

    LOADG_A(0); STS_A(0);
    LOADG_B(0); STS_B(0);
    __syncthreads();

    for (int kt = 0; kt < 32; kt++) {
        int buf = kt & 1;
        bool more = (kt < 31);
        if (more) LOADG_A(kt + 1);
        COMPUTE_KS(buf, 0);
        COMPUTE_KS(buf, 1);
        if (more) { STS_A(buf ^ 1); LOADG_B(kt + 1); }
        COMPUTE_KS(buf, 2);
        COMPUTE_KS(buf, 3);
        if (more) STS_B(buf ^ 1);
        __syncthreads();
    }

    #pragma unroll
    for (int mt = 0; mt < 4; mt++) {
        #pragma unroll
        for (int half = 0; half < 2; half++) {
            int m = bm * 128 + wm + mt * 16 + q + half * 8;
            #pragma unroll
            for (int nt = 0; nt < 4; nt++) {
                int n = bn * 128 + wn + nt * 8 + 2 * r;
                float v0 = acc[mt * 4 + nt][half * 2 + 0];
                float v1 = acc[mt * 4 + nt][half * 2 + 1];
                if (EPI == 0) {
                    int b_ = m >> 11, t_ = m & 2047, h_ = n >> 6, s_ = n & 63;
                    float2 ov = make_float2(v0, v1);
                    *(float2*)(C + ((((size_t)b_ * Hh + h_) * Tt + t_) << 6) + s_) = ov;
                } else if (EPI == 1) {
                    size_t idx = (size_t)m * Dd + n;
                    float2 a1 = *(const float2*)(add1 + idx);
                    float2 ov = make_float2(v0 + bias[n] + a1.x, v1 + bias[n + 1] + a1.y);
                    *(float2*)(C + idx) = ov;
                } else if (EPI == 2) {
                    float u0 = v0 + bias[n], u1 = v1 + bias[n + 1];
                    float2 ov = make_float2(u0 > 0.f ? u0 : 0.f, u1 > 0.f ? u1 : 0.f);
                    *(float2*)(C + (size_t)m * Dd + n) = ov;
                } else {
                    size_t idx = (size_t)m * Dd + n;
                    float2 a1 = *(const float2*)(add1 + idx);
                    float2 a2 = *(const float2*)(add2 + idx);
                    float2 ov = make_float2(v0 + bias[n] + a1.x + a2.x,
                                            v1 + bias[n + 1] + a1.y + a2.y);
                    *(float2*)(C + idx) = ov;
                }
            }
        }
    }
#undef LOADG_A
#undef STS_A
#undef LOADG_B
#undef STS_B
#undef COMPUTE_KS
}

// ---------------- TF32 tensor-core flash attention ----------------
// grid: (16, H, B), qi = 15 - bx (heavy tiles first). Block 256 = 8 warps.
// Q tile 128 rows (warp w owns rows w*16..w*16+15), key tile 64.
// Pitches: Qs/Ks/Ps 68 (≡4 mod 32 → frag banks 4q+r, conflict-free),
//          Vs 72 (≡8 mod 32 → frag banks 8r+q, conflict-free).
#define QP 68
#define KP 68
#define VP 72
#define PP 68
#define ATTN_SMEM ((128*QP + 64*KP + 64*VP + 128*PP) * 4)   // 105472 B

__global__ void __launch_bounds__(256, 2) attn_k(
    const float* __restrict__ Kg, const float* __restrict__ Vg,
    float* __restrict__ cat)
{
    extern __shared__ float sm[];
    float* Qs = sm;
    float* Ks = Qs + 128 * QP;
    float* Vs = Ks + 64 * KP;
    float* Ps = Vs + 64 * VP;

    const int qi = (int)(gridDim.x - 1) - (int)blockIdx.x;
    const int h = blockIdx.y, b = blockIdx.z;
    const int tid = threadIdx.x, lane = tid & 31, w = tid >> 5;
    const int q = lane >> 2, r = lane & 3;

    const float* Kb = Kg + (((size_t)b * Hh + h) * Tt) * HSs;
    const float* Vb = Vg + (((size_t)b * Hh + h) * Tt) * HSs;

    const float scale = 9.313225746154785e-10f;  // 64^-5 = 2^-30

    // load Q tile (pre-scaled, tf32-rounded)
    #pragma unroll
    for (int i = 0; i < 8; i++) {
        int f = tid + i * 256;
        int rr = f >> 4, cc = (f & 15) << 2;
        float4 v = *(const float4*)(Kb + (size_t)(qi * 128 + rr) * 64 + cc);
        float* p = Qs + rr * QP + cc;
        p[0] = tf32r(v.x * scale); p[1] = tf32r(v.y * scale);
        p[2] = tf32r(v.z * scale); p[3] = tf32r(v.w * scale);
    }

    float m0 = -1e30f, m1 = -1e30f, l0 = 0.f, l1 = 0.f;
    float oacc[8][4];
    #pragma unroll
    for (int nt = 0; nt < 8; nt++)
        #pragma unroll
        for (int i = 0; i < 4; i++) oacc[nt][i] = 0.f;

    const int grow0 = qi * 128 + w * 16 + q;
    const int grow1 = grow0 + 8;

    const int jmax = 2 * qi + 1;
    for (int j = 0; j <= jmax; j++) {
        __syncthreads();   // K/V/(Q on j=0) tiles safe to (over)write
        #pragma unroll
        for (int i = 0; i < 4; i++) {
            int f = tid + i * 256;
            int rr = f >> 4, cc = (f & 15) << 2;
            float4 kv = *(const float4*)(Kb + (size_t)(j * 64 + rr) * 64 + cc);
            float4 vv = *(const float4*)(Vb + (size_t)(j * 64 + rr) * 64 + cc);
            float* pk = Ks + rr * KP + cc;
            pk[0] = tf32r(kv.x); pk[1] = tf32r(kv.y);
            pk[2] = tf32r(kv.z); pk[3] = tf32r(kv.w);
            float* pv = Vs + rr * VP + cc;
            pv[0] = tf32r(vv.x); pv[1] = tf32r(vv.y);
            pv[2] = tf32r(vv.z); pv[3] = tf32r(vv.w);
        }
        __syncthreads();

        // ---- S = Q K^T (128x64, warp: 16x64) ----
        float sacc[8][4];
        #pragma unroll
        for (int nt = 0; nt < 8; nt++)
            #pragma unroll
            for (int i = 0; i < 4; i++) sacc[nt][i] = 0.f;

        #pragma unroll
        for (int ks = 0; ks < 8; ks++) {
            const float* ap = Qs + (w * 16 + q) * QP + ks * 8 + r;
            unsigned afr[4];
            afr[0] = *(const unsigned*)(ap);
            afr[1] = *(const unsigned*)(ap + 8 * QP);
            afr[2] = *(const unsigned*)(ap + 4);
            afr[3] = *(const unsigned*)(ap + 8 * QP + 4);
            #pragma unroll
            for (int nt = 0; nt < 8; nt++) {
                const float* bp = Ks + (nt * 8 + q) * KP + ks * 8 + r;
                unsigned bfr[2];
                bfr[0] = *(const unsigned*)(bp);
                bfr[1] = *(const unsigned*)(bp + 4);
                mma_tf32(sacc[nt], afr, bfr);
            }
        }

        // ---- mask + online softmax (2 rows per thread) ----
        const bool needmask = (j >= 2 * qi);
        if (needmask) {
            #pragma unroll
            for (int nt = 0; nt < 8; nt++) {
                int c0 = j * 64 + nt * 8 + 2 * r;
                if (c0 > grow0)     sacc[nt][0] = -1e30f;
                if (c0 + 1 > grow0) sacc[nt][1] = -1e30f;
                if (c0 > grow1)     sacc[nt][2] = -1e30f;
                if (c0 + 1 > grow1) sacc[nt][3] = -1e30f;
            }
        }
        float mx0 = -1e30f, mx1 = -1e30f;
        #pragma unroll
        for (int nt = 0; nt < 8; nt++) {
            mx0 = fmaxf(mx0, fmaxf(sacc[nt][0], sacc[nt][1]));
            mx1 = fmaxf(mx1, fmaxf(sacc[nt][2], sacc[nt][3]));
        }
        mx0 = fmaxf(mx0, __shfl_xor_sync(0xffffffffu, mx0, 1));
        mx0 = fmaxf(mx0, __shfl_xor_sync(0xffffffffu, mx0, 2));
        mx1 = fmaxf(mx1, __shfl_xor_sync(0xffffffffu, mx1, 1));
        mx1 = fmaxf(mx1, __shfl_xor_sync(0xffffffffu, mx1, 2));

        float mn0 = fmaxf(m0, mx0), mn1 = fmaxf(m1, mx1);
        float al0 = __expf(m0 - mn0), al1 = __expf(m1 - mn1);
        m0 = mn0; m1 = mn1;

        float rs0 = 0.f, rs1 = 0.f;
        #pragma unroll
        for (int nt = 0; nt < 8; nt++) {
            float p0 = __expf(sacc[nt][0] - mn0);
            float p1 = __expf(sacc[nt][1] - mn0);
            float p2 = __expf(sacc[nt][2] - mn1);
            float p3 = __expf(sacc[nt][3] - mn1);
            rs0 += p0 + p1; rs1 += p2 + p3;
            float* pp0 = Ps + (w * 16 + q) * PP + nt * 8 + 2 * r;
            *(float2*)pp0 = make_float2(tf32r(p0), tf32r(p1));
            *(float2*)(pp0 + 8 * PP) = make_float2(tf32r(p2), tf32r(p3));
        }
        rs0 += __shfl_xor_sync(0xffffffffu, rs0, 1);
        rs0 += __shfl_xor_sync(0xffffffffu, rs0, 2);
        rs1 += __shfl_xor_sync(0xffffffffu, rs1, 1);
        rs1 += __shfl_xor_sync(0xffffffffu, rs1, 2);
        l0 = l0 * al0 + rs0;
        l1 = l1 * al1 + rs1;
        #pragma unroll
        for (int nt = 0; nt < 8; nt++) {
            oacc[nt][0] *= al0; oacc[nt][1] *= al0;
            oacc[nt][2] *= al1; oacc[nt][3] *= al1;
        }
        __syncwarp();   // P rows are warp-private; order STS vs LDS within warp

        // ---- O += P @ V (warp: 16x64) ----
        #pragma unroll
        for (int ks = 0; ks < 8; ks++) {
            const float* ap = Ps + (w * 16 + q) * PP + ks * 8 + r;
            unsigned afr[4];
            afr[0] = *(const unsigned*)(ap);
            afr[1] = *(const unsigned*)(ap + 8 * PP);
            afr[2] = *(const unsigned*)(ap + 4);
            afr[3] = *(const unsigned*)(ap + 8 * PP + 4);
            #pragma unroll
            for (int nt = 0; nt < 8; nt++) {
                const float* bp = Vs + (ks * 8 + r) * VP + nt * 8 + q;
                unsigned bfr[2];
                bfr[0] = *(const unsigned*)(bp);
                bfr[1] = *(const unsigned*)(bp + 4 * VP);
                mma_tf32(oacc[nt], afr, bfr);
            }
        }
    }

    // ---- finalize ----
    float inv0 = 1.f / l0, inv1 = 1.f / l1;
    #pragma unroll
    for (int nt = 0; nt < 8; nt++) {
        float* d0 = cat + ((size_t)b * Tt + grow0) * Dd + h * 64 + nt * 8 + 2 * r;
        *(float2*)d0 = make_float2(oacc[nt][0] * inv0, oacc[nt][1] * inv0);
        float* d1 = cat + ((size_t)b * Tt + grow1) * Dd + h * 64 + nt * 8 + 2 * r;
        *(float2*)d1 = make_float2(oacc[nt][2] * inv1, oacc[nt][3] * inv1);
    }
}

// ---------------- LayerNorm: one block per row of 1024 ----------------
__global__ void __launch_bounds__(256) ln_k(
    const float* __restrict__ in, const float* __restrict__ g,
    const float* __restrict__ bb, float* __restrict__ out)
{
    __shared__ float rs[8], rq[8];
    int row = blockIdx.x;
    const float4 v = ((const float4*)(in + (size_t)row * Dd))[threadIdx.x];
    float s = v.x + v.y + v.z + v.w;
    float q = v.x * v.x + v.y * v.y + v.z * v.z + v.w * v.w;
    #pragma unroll
    for (int w = 16; w >= 1; w >>= 1) {
        s += __shfl_xor_sync(0xffffffffu, s, w);
        q += __shfl_xor_sync(0xffffffffu, q, w);
    }
    int warp = threadIdx.x >> 5, lane = threadIdx.x & 31;
    if (lane == 0) { rs[warp] = s; rq[warp] = q; }
    __syncthreads();
    if (threadIdx.x == 0) {
        float ts = 0.f, tq = 0.f;
        #pragma unroll
        for (int i = 0; i < 8; i++) { ts += rs[i]; tq += rq[i]; }
        float mean = ts * (1.f / 1024.f);
        float var  = tq * (1.f / 1024.f) - mean * mean;
        rs[0] = mean;
        rq[0] = rsqrtf(var + 1e-5f);
    }
    __syncthreads();
    float mean = rs[0], inv = rq[0];
    const float4 g4 = ((const float4*)g )[threadIdx.x];
    const float4 b4 = ((const float4*)bb)[threadIdx.x];
    float4 ov;
    ov.x = (v.x - mean) * inv * g4.x + b4.x;
    ov.y = (v.y - mean) * inv * g4.y + b4.y;
    ov.z = (v.z - mean) * inv * g4.z + b4.z;
    ov.w = (v.w - mean) * inv * g4.w + b4.w;
    ((float4*)(out + (size_t)row * Dd))[threadIdx.x] = ov;
}

// ---------------- driver ----------------
extern "C" void kernel_launch(void* const* d_in, const int* in_sizes, int n_in,
                              void* d_out, int out_size)
{
    const float* x   = (const float*)d_in[0];
    const float* Wk  = (const float*)d_in[1];
    const float* Wv  = (const float*)d_in[2];
    const float* Wo  = (const float*)d_in[3];
    const float* bo  = (const float*)d_in[4];
    const float* g1  = (const float*)d_in[5];
    const float* b1  = (const float*)d_in[6];
    const float* Wf1 = (const float*)d_in[7];
    const float* bf1 = (const float*)d_in[8];
    const float* Wf2 = (const float*)d_in[9];
    const float* bf2 = (const float*)d_in[10];
    const float* g2  = (const float*)d_in[11];
    const float* b2  = (const float*)d_in[12];
    float* out = (float*)d_out;

    float *pK, *pV, *pcat, *py, *pnorm, *ph1, *pz;
    cudaGetSymbolAddress((void**)&pK,    g_K);
    cudaGetSymbolAddress((void**)&pV,    g_V);
    cudaGetSymbolAddress((void**)&pcat,  g_cat);
    cudaGetSymbolAddress((void**)&py,    g_y);
    cudaGetSymbolAddress((void**)&pnorm, g_norm);
    cudaGetSymbolAddress((void**)&ph1,   g_h1);
    cudaGetSymbolAddress((void**)&pz,    g_z);

    cudaFuncSetAttribute(attn_k, cudaFuncAttributeMaxDynamicSharedMemorySize, ATTN_SMEM);
    cudaFuncSetAttribute(tgemm_k<1,0>, cudaFuncAttributeMaxDynamicSharedMemorySize, GEMM_SMEM);
    cudaFuncSetAttribute(tgemm_k<0,1>, cudaFuncAttributeMaxDynamicSharedMemorySize, GEMM_SMEM);
    cudaFuncSetAttribute(tgemm_k<0,2>, cudaFuncAttributeMaxDynamicSharedMemorySize, GEMM_SMEM);
    cudaFuncSetAttribute(tgemm_k<0,3>, cudaFuncAttributeMaxDynamicSharedMemorySize, GEMM_SMEM);

    dim3 gg(8, 64), tb(256);

    // 1-2: K and V projections
    tgemm_k<1, 0><<<gg, tb, GEMM_SMEM>>>(x, Wk, pK, nullptr, nullptr, nullptr);
    tgemm_k<1, 0><<<gg, tb, GEMM_SMEM>>>(x, Wv, pV, nullptr, nullptr, nullptr);

    // 3: causal flash attention (tensor cores)
    attn_k<<<dim3(Tt / 128, Hh, Bb), 256, ATTN_SMEM>>>(pK, pV, pcat);

    // 4: y = cat @ Wo + bo + x
    tgemm_k<0, 1><<<gg, tb, GEMM_SMEM>>>(pcat, Wo, py, bo, x, nullptr);

    // 5: norm = LN1(y)
    ln_k<<<Mm, 256>>>(py, g1, b1, pnorm);

    // 6: h1 = relu(norm @ Wf1 + bf1)
    tgemm_k<0, 2><<<gg, tb, GEMM_SMEM>>>(pnorm, Wf1, ph1, bf1, nullptr, nullptr);

    // 7: z = h1 @ Wf2 + bf2 + norm + x
    tgemm_k<0, 3><<<gg, tb, GEMM_SMEM>>>(ph1, Wf2, pz, bf2, pnorm, x);

    // 8: out = LN2(z)
    ln_k<<<Mm, 256>>>(pz, g2, b2, out);
}